// round 6
// baseline (speedup 1.0000x reference)
#include <cuda_runtime.h>
#include <cstdint>

#define PNUM 8
#define DDIM 512
#define ADIM 64
#define XDIM 576
#define HDIM 1024
#define BCAP 16384
#define MAXT 136

// ---------------- device scratch ----------------
__device__ int d_cursor[PNUM];
__device__ int d_is64;
__device__ int d_row_id[PNUM * BCAP];
__device__ __align__(128) float d_xbuf[(size_t)MAXT * 128 * XDIM];        // 40 MB, tf32-rounded gathered x
__device__ __align__(128) float d_hbuf[(size_t)MAXT * 128 * HDIM];        // 71 MB, tf32-rounded h
__device__ __align__(128) float d_w1t[(size_t)PNUM * HDIM * XDIM];        // [p][n][k], tf32-rounded
__device__ __align__(128) float d_w2t[(size_t)PNUM * DDIM * HDIM];        // [p][n][k], tf32-rounded

// ---------------- helpers ----------------
__device__ __forceinline__ void cpasync16(uint32_t dst, const void* src) {
    asm volatile("cp.async.cg.shared.global [%0], [%1], 16;\n"
                 :: "r"(dst), "l"(src) : "memory");
}
#define CP_COMMIT() asm volatile("cp.async.commit_group;\n" ::: "memory")
#define CP_WAIT(n)  asm volatile("cp.async.wait_group " #n ";\n" ::: "memory")

__device__ __forceinline__ uint32_t smem_u32(const void* p) {
    uint32_t a;
    asm("{ .reg .u64 t; cvta.to.shared.u64 t, %1; cvt.u32.u64 %0, t; }" : "=r"(a) : "l"(p));
    return a;
}
__device__ __forceinline__ float tf32r(float x) {
    uint32_t u;
    asm("cvt.rn.tf32.f32 %0, %1;" : "=r"(u) : "f"(x));
    return __uint_as_float(u);
}
__device__ __forceinline__ void ldsm4(uint32_t* r, uint32_t addr) {
    asm volatile("ldmatrix.sync.aligned.m8n8.x4.shared.b16 {%0,%1,%2,%3}, [%4];"
                 : "=r"(r[0]), "=r"(r[1]), "=r"(r[2]), "=r"(r[3]) : "r"(addr));
}
__device__ __forceinline__ void mma_tf32(float* c, const uint32_t* a, uint32_t b0, uint32_t b1) {
    asm volatile(
        "mma.sync.aligned.m16n8k8.row.col.f32.tf32.tf32.f32 "
        "{%0,%1,%2,%3}, {%4,%5,%6,%7}, {%8,%9}, {%0,%1,%2,%3};"
        : "+f"(c[0]), "+f"(c[1]), "+f"(c[2]), "+f"(c[3])
        : "r"(a[0]), "r"(a[1]), "r"(a[2]), "r"(a[3]), "r"(b0), "r"(b1));
}
__device__ __forceinline__ int get_pidx(const void* pi, int b) {
    if (d_is64) return (int)(((const long long*)pi)[b]);
    return ((const int*)pi)[b];
}

// CTA tile -> (policy, local tile, vrows, ridbase) from cursors
struct Meta { int p, vrows, ridbase; };
__device__ __forceinline__ Meta tile_meta(int t) {
    int acc = 0, p = -1, lt = 0, c = 0;
#pragma unroll
    for (int q = 0; q < PNUM; q++) {
        int cq = d_cursor[q];
        int nt = (cq + 127) >> 7;
        if (p < 0 && t < acc + nt) { p = q; lt = t - acc; c = cq; }
        acc += nt;
    }
    Meta m; m.p = p;
    if (p >= 0) {
        int rem = c - lt * 128;
        m.vrows = rem < 128 ? rem : 128;
        m.ridbase = p * BCAP + lt * 128;
    } else { m.vrows = 0; m.ridbase = 0; }
    return m;
}

// ---------------- setup ----------------
__global__ void k_init(const int* pi32, int B) {
    int t = threadIdx.x;
    if (t < PNUM) d_cursor[t] = 0;
    int n = B < 64 ? B : 64;
    int bad = 0;
#pragma unroll
    for (int r = 0; r < 2; r++) {
        int i = t + 32 * r;
        if (i < n) {
            int lo = pi32[2 * i], hi = pi32[2 * i + 1];
            bad |= (hi != 0) || (lo < 0) || (lo >= PNUM);
        }
    }
    unsigned m = __ballot_sync(0xFFFFFFFF, bad);
    if (t == 0) d_is64 = (m == 0) ? 1 : 0;
}
__global__ void k_scan(const void* __restrict__ pi, int B) {
    int b = blockIdx.x * blockDim.x + threadIdx.x;
    if (b < B) {
        int p = get_pidx(pi, b);
        int pos = atomicAdd(&d_cursor[p], 1);
        d_row_id[p * BCAP + pos] = b;
    }
}

// Transpose + tf32-round weights (n-major [p][n][k])
#define W1BLK (PNUM * 18 * 32)
#define W2BLK (PNUM * 32 * 16)
__global__ __launch_bounds__(256) void k_tw(const float* __restrict__ W1,
                                            const float* __restrict__ W2) {
    __shared__ float s[32][33];
    int bid = blockIdx.x;
    int tx = threadIdx.x & 31, ty = threadIdx.x >> 5;
    if (bid < W1BLK) {
        int p = bid / (18 * 32), r = bid % (18 * 32), rt = r / 32, ct = r % 32;
        const float* in = W1 + (size_t)p * XDIM * HDIM;
        float* out = d_w1t + (size_t)p * HDIM * XDIM;
        int r0 = rt * 32, c0 = ct * 32;
#pragma unroll
        for (int i = 0; i < 4; i++)
            s[ty + 8 * i][tx] = in[(size_t)(r0 + ty + 8 * i) * HDIM + c0 + tx];
        __syncthreads();
#pragma unroll
        for (int i = 0; i < 4; i++)
            out[(size_t)(c0 + ty + 8 * i) * XDIM + r0 + tx] = tf32r(s[tx][ty + 8 * i]);
    } else {
        int b2 = bid - W1BLK;
        int p = b2 / (32 * 16), r = b2 % (32 * 16), rt = r / 16, ct = r % 16;
        const float* in = W2 + (size_t)p * HDIM * DDIM;
        float* out = d_w2t + (size_t)p * DDIM * HDIM;
        int r0 = rt * 32, c0 = ct * 32;
#pragma unroll
        for (int i = 0; i < 4; i++)
            s[ty + 8 * i][tx] = in[(size_t)(r0 + ty + 8 * i) * DDIM + c0 + tx];
        __syncthreads();
#pragma unroll
        for (int i = 0; i < 4; i++)
            out[(size_t)(c0 + ty + 8 * i) * HDIM + r0 + tx] = tf32r(s[tx][ty + 8 * i]);
    }
}

// Gather x = [latents|actions] rows into padded, tf32-rounded d_xbuf
__global__ __launch_bounds__(256) void k_gx(const float* __restrict__ latents,
                                            const float* __restrict__ actions) {
    __shared__ int rid_s[128];
    __shared__ Meta sm;
    int tid = threadIdx.x, t = blockIdx.x;
    if (tid == 0) sm = tile_meta(t);
    __syncthreads();
    if (sm.p < 0) return;
    if (tid < 128) rid_s[tid] = (tid < sm.vrows) ? d_row_id[sm.ridbase + tid] : -1;
    __syncthreads();
    float* xb = d_xbuf + (size_t)t * 128 * XDIM;
#pragma unroll
    for (int tt = 0; tt < 72; tt++) {
        int j = tid + tt * 256;              // 128 rows * 144 float4-segs
        int row = j / 144, s = j % 144;
        int b = rid_s[row];
        float4 v = make_float4(0.f, 0.f, 0.f, 0.f);
        if (b >= 0)
            v = (s < 128) ? *(const float4*)(latents + (size_t)b * DDIM + s * 4)
                          : *(const float4*)(actions + (size_t)b * ADIM + (s - 128) * 4);
        v.x = tf32r(v.x); v.y = tf32r(v.y); v.z = tf32r(v.z); v.w = tf32r(v.w);
        *(float4*)(xb + (size_t)row * XDIM + s * 4) = v;
    }
}

// ---------------- SMEM layout ----------------
#define TSTRIDE 36
#define TBYTES  (128 * TSTRIDE * 4)   // 18432
#define STAGE   (2 * TBYTES)          // 36864
#define NSTG    3
#define SMEM_TOTAL (NSTG * STAGE)     // 110592

// ---------------- tf32 GEMM: 128x128 CTA tile, 8 warps of 64x32, BK=32, 3-stage ----------------
template <int LAYER>
__global__ __launch_bounds__(256, 2) void k_mma(
    const float* __restrict__ bias, float* __restrict__ out)
{
    constexpr int KDIM = (LAYER == 1) ? XDIM : HDIM;
    constexpr int NDIM = (LAYER == 1) ? HDIM : DDIM;
    constexpr int KT   = KDIM / 32;

    extern __shared__ char smem[];
    __shared__ int rid_s[128];
    __shared__ Meta sm;
    const uint32_t sb = smem_u32(smem);
    const int tid = threadIdx.x;
    const int t = blockIdx.y;

    if (tid == 0) sm = tile_meta(t);
    __syncthreads();
    const int p = sm.p;
    if (p < 0) return;
    if (LAYER == 2 && tid < 128)
        rid_s[tid] = (tid < sm.vrows) ? d_row_id[sm.ridbase + tid] : -1;
    const int n0 = blockIdx.x * 128;
    const int row0 = t * 128;

    // ---- hoisted streaming pointers ----
    const int lrow = tid >> 3, lseg = tid & 7;
    const float* aptr = ((LAYER == 1) ? d_xbuf : d_hbuf)
                        + (size_t)(row0 + lrow) * KDIM + lseg * 4;
    const float* bptr = ((LAYER == 1)
                        ? d_w1t + (size_t)p * HDIM * XDIM
                        : d_w2t + (size_t)p * DDIM * HDIM)
                        + (size_t)(n0 + lrow) * KDIM + lseg * 4;
    const uint32_t ldst = (uint32_t)lrow * (TSTRIDE * 4) + lseg * 16;

    auto load = [&](int slot) {
        const uint32_t ab = sb + slot * STAGE;
#pragma unroll
        for (int tt = 0; tt < 4; tt++)
            cpasync16(ab + ldst + tt * (32 * TSTRIDE * 4), aptr + (size_t)tt * 32 * KDIM);
#pragma unroll
        for (int tt = 0; tt < 4; tt++)
            cpasync16(ab + TBYTES + ldst + tt * (32 * TSTRIDE * 4), bptr + (size_t)tt * 32 * KDIM);
        CP_COMMIT();
        aptr += 32; bptr += 32;
    };

    // ---- fragment geometry: 2(m) x 4(n) warps, 64x32 tiles ----
    const int lane = tid & 31, warp = tid >> 5;
    const int wm = warp >> 2, wn = warp & 3;
    const int g = lane >> 2, tq = lane & 3;
    const uint32_t fo = ((uint32_t)(lane & 15) * TSTRIDE + ((lane & 16) >> 2)) * 4;
    const uint32_t ao = (uint32_t)(wm * 64) * TSTRIDE * 4 + fo;
    const uint32_t bo = (uint32_t)(wn * 32) * TSTRIDE * 4 + fo;

    float acc[4][4][4];
#pragma unroll
    for (int i = 0; i < 4; i++)
#pragma unroll
        for (int j = 0; j < 4; j++)
#pragma unroll
            for (int q = 0; q < 4; q++) acc[i][j][q] = 0.f;

    load(0); load(1); load(2);

    int slot = 0;
    for (int c = 0; c < KT; c++) {
        if (c + 2 < KT)      CP_WAIT(2);
        else if (c + 1 < KT) CP_WAIT(1);
        else                 CP_WAIT(0);
        __syncthreads();

        const uint32_t Ab = sb + slot * STAGE;
        const uint32_t Bb = Ab + TBYTES;
#pragma unroll
        for (int ks = 0; ks < 4; ks++) {
            uint32_t a[4][4], b[2][4];
#pragma unroll
            for (int i = 0; i < 4; i++)
                ldsm4(a[i], Ab + ao + (uint32_t)(i * 16 * TSTRIDE + ks * 8) * 4);
#pragma unroll
            for (int jj = 0; jj < 2; jj++)
                ldsm4(b[jj], Bb + bo + (uint32_t)(jj * 16 * TSTRIDE + ks * 8) * 4);
#pragma unroll
            for (int i = 0; i < 4; i++)
#pragma unroll
                for (int jj = 0; jj < 2; jj++) {
                    mma_tf32(acc[i][2 * jj],     a[i], b[jj][0], b[jj][2]);
                    mma_tf32(acc[i][2 * jj + 1], a[i], b[jj][1], b[jj][3]);
                }
        }
        __syncthreads();
        if (c + 3 < KT) load(slot);
        slot = (slot == 2) ? 0 : slot + 1;
    }

    // ---- epilogue ----
    const float* bp = bias + p * NDIM + n0;
    if (LAYER == 1) {
        float* hb = d_hbuf + (size_t)row0 * HDIM + n0;
#pragma unroll
        for (int j = 0; j < 4; j++) {
            int col = wn * 32 + j * 8 + 2 * tq;
            float bx = bp[col], by = bp[col + 1];
#pragma unroll
            for (int i = 0; i < 4; i++) {
                int r0 = wm * 64 + i * 16 + g;
                float2 v0 = make_float2(tf32r(fmaxf(acc[i][j][0] + bx, 0.f)),
                                        tf32r(fmaxf(acc[i][j][1] + by, 0.f)));
                float2 v1 = make_float2(tf32r(fmaxf(acc[i][j][2] + bx, 0.f)),
                                        tf32r(fmaxf(acc[i][j][3] + by, 0.f)));
                *(float2*)(hb + (size_t)r0 * HDIM + col)       = v0;
                *(float2*)(hb + (size_t)(r0 + 8) * HDIM + col) = v1;
            }
        }
    } else {
#pragma unroll
        for (int i = 0; i < 4; i++) {
            int r0 = wm * 64 + i * 16 + g;
            int b0 = rid_s[r0], b1i = rid_s[r0 + 8];
#pragma unroll
            for (int j = 0; j < 4; j++) {
                int col = wn * 32 + j * 8 + 2 * tq;
                float bx = bp[col], by = bp[col + 1];
                if (b0 >= 0)
                    *(float2*)(out + (size_t)b0 * DDIM + n0 + col) =
                        make_float2(acc[i][j][0] + bx, acc[i][j][1] + by);
                if (b1i >= 0)
                    *(float2*)(out + (size_t)b1i * DDIM + n0 + col) =
                        make_float2(acc[i][j][2] + bx, acc[i][j][3] + by);
            }
        }
    }
}

// ---------------- launch ----------------
extern "C" void kernel_launch(void* const* d_in, const int* in_sizes, int n_in,
                              void* d_out, int out_size)
{
    const float* latents = (const float*)d_in[0];
    const float* actions = (const float*)d_in[1];
    const void*  pidx    = d_in[2];
    const float* W1      = (const float*)d_in[3];
    const float* b1      = (const float*)d_in[4];
    const float* W2      = (const float*)d_in[5];
    const float* b2      = (const float*)d_in[6];
    float*       out     = (float*)d_out;

    int B = in_sizes[0] / DDIM;               // 16384
    int gy = B / 128 + PNUM - 1;              // 135 max tiles

    cudaFuncSetAttribute(k_mma<1>, cudaFuncAttributeMaxDynamicSharedMemorySize, SMEM_TOTAL);
    cudaFuncSetAttribute(k_mma<2>, cudaFuncAttributeMaxDynamicSharedMemorySize, SMEM_TOTAL);

    k_init<<<1, 32>>>((const int*)pidx, B);
    k_scan<<<(B + 255) / 256, 256>>>(pidx, B);
    k_tw<<<W1BLK + W2BLK, 256>>>(W1, W2);
    k_gx<<<gy, 256>>>(latents, actions);

    k_mma<1><<<dim3(HDIM / 128, gy), 256, SMEM_TOTAL>>>(b1, nullptr);
    k_mma<2><<<dim3(DDIM / 128, gy), 256, SMEM_TOTAL>>>(b2, out);
}

// round 7
// speedup vs baseline: 1.4464x; 1.4464x over previous
#include <cuda_runtime.h>
#include <cuda_fp16.h>
#include <cstdint>

#define PNUM 8
#define DDIM 512
#define ADIM 64
#define XDIM 576
#define HDIM 1024
#define BCAP 16384
#define MAXT 136

// ---------------- device scratch ----------------
__device__ int d_cursor[PNUM];
__device__ int d_is64;
__device__ int d_row_id[PNUM * BCAP];
__device__ __align__(128) __half d_xbuf[(size_t)MAXT * 128 * XDIM];   // 20 MB fp16 gathered x
__device__ __align__(128) __half d_hbuf[(size_t)MAXT * 128 * HDIM];   // 35 MB fp16 h
__device__ __align__(128) __half d_w1t[(size_t)PNUM * HDIM * XDIM];   // [p][n][k] fp16
__device__ __align__(128) __half d_w2t[(size_t)PNUM * DDIM * HDIM];   // [p][n][k] fp16

// ---------------- helpers ----------------
__device__ __forceinline__ void cpasync16(uint32_t dst, const void* src) {
    asm volatile("cp.async.cg.shared.global [%0], [%1], 16;\n"
                 :: "r"(dst), "l"(src) : "memory");
}
#define CP_COMMIT() asm volatile("cp.async.commit_group;\n" ::: "memory")
#define CP_WAIT(n)  asm volatile("cp.async.wait_group " #n ";\n" ::: "memory")

__device__ __forceinline__ uint32_t smem_u32(const void* p) {
    uint32_t a;
    asm("{ .reg .u64 t; cvta.to.shared.u64 t, %1; cvt.u32.u64 %0, t; }" : "=r"(a) : "l"(p));
    return a;
}
__device__ __forceinline__ void ldsm4(uint32_t* r, uint32_t addr) {
    asm volatile("ldmatrix.sync.aligned.m8n8.x4.shared.b16 {%0,%1,%2,%3}, [%4];"
                 : "=r"(r[0]), "=r"(r[1]), "=r"(r[2]), "=r"(r[3]) : "r"(addr));
}
__device__ __forceinline__ void mma_f16(float* c, const uint32_t* a, uint32_t b0, uint32_t b1) {
    asm volatile(
        "mma.sync.aligned.m16n8k16.row.col.f32.f16.f16.f32 "
        "{%0,%1,%2,%3}, {%4,%5,%6,%7}, {%8,%9}, {%0,%1,%2,%3};"
        : "+f"(c[0]), "+f"(c[1]), "+f"(c[2]), "+f"(c[3])
        : "r"(a[0]), "r"(a[1]), "r"(a[2]), "r"(a[3]), "r"(b0), "r"(b1));
}
__device__ __forceinline__ int get_pidx(const void* pi, int b) {
    if (d_is64) return (int)(((const long long*)pi)[b]);
    return ((const int*)pi)[b];
}

struct Meta { int p, vrows, ridbase; };
__device__ __forceinline__ Meta tile_meta(int t) {
    int acc = 0, p = -1, lt = 0, c = 0;
#pragma unroll
    for (int q = 0; q < PNUM; q++) {
        int cq = d_cursor[q];
        int nt = (cq + 127) >> 7;
        if (p < 0 && t < acc + nt) { p = q; lt = t - acc; c = cq; }
        acc += nt;
    }
    Meta m; m.p = p;
    if (p >= 0) {
        int rem = c - lt * 128;
        m.vrows = rem < 128 ? rem : 128;
        m.ridbase = p * BCAP + lt * 128;
    } else { m.vrows = 0; m.ridbase = 0; }
    return m;
}

// ---------------- setup ----------------
__global__ void k_init(const int* pi32, int B) {
    int t = threadIdx.x;
    if (t < PNUM) d_cursor[t] = 0;
    int n = B < 64 ? B : 64;
    int bad = 0;
#pragma unroll
    for (int r = 0; r < 2; r++) {
        int i = t + 32 * r;
        if (i < n) {
            int lo = pi32[2 * i], hi = pi32[2 * i + 1];
            bad |= (hi != 0) || (lo < 0) || (lo >= PNUM);
        }
    }
    unsigned m = __ballot_sync(0xFFFFFFFF, bad);
    if (t == 0) d_is64 = (m == 0) ? 1 : 0;
}
__global__ void k_scan(const void* __restrict__ pi, int B) {
    int b = blockIdx.x * blockDim.x + threadIdx.x;
    if (b < B) {
        int p = get_pidx(pi, b);
        int pos = atomicAdd(&d_cursor[p], 1);
        d_row_id[p * BCAP + pos] = b;
    }
}

// Transpose + fp16-convert weights (n-major [p][n][k])
#define W1BLK (PNUM * 18 * 32)
#define W2BLK (PNUM * 32 * 16)
__global__ __launch_bounds__(256) void k_tw(const float* __restrict__ W1,
                                            const float* __restrict__ W2) {
    __shared__ float s[32][33];
    int bid = blockIdx.x;
    int tx = threadIdx.x & 31, ty = threadIdx.x >> 5;
    if (bid < W1BLK) {
        int p = bid / (18 * 32), r = bid % (18 * 32), rt = r / 32, ct = r % 32;
        const float* in = W1 + (size_t)p * XDIM * HDIM;
        __half* out = d_w1t + (size_t)p * HDIM * XDIM;
        int r0 = rt * 32, c0 = ct * 32;
#pragma unroll
        for (int i = 0; i < 4; i++)
            s[ty + 8 * i][tx] = in[(size_t)(r0 + ty + 8 * i) * HDIM + c0 + tx];
        __syncthreads();
#pragma unroll
        for (int i = 0; i < 4; i++)
            out[(size_t)(c0 + ty + 8 * i) * XDIM + r0 + tx] = __float2half_rn(s[tx][ty + 8 * i]);
    } else {
        int b2 = bid - W1BLK;
        int p = b2 / (32 * 16), r = b2 % (32 * 16), rt = r / 16, ct = r % 16;
        const float* in = W2 + (size_t)p * HDIM * DDIM;
        __half* out = d_w2t + (size_t)p * DDIM * HDIM;
        int r0 = rt * 32, c0 = ct * 32;
#pragma unroll
        for (int i = 0; i < 4; i++)
            s[ty + 8 * i][tx] = in[(size_t)(r0 + ty + 8 * i) * DDIM + c0 + tx];
        __syncthreads();
#pragma unroll
        for (int i = 0; i < 4; i++)
            out[(size_t)(c0 + ty + 8 * i) * HDIM + r0 + tx] = __float2half_rn(s[tx][ty + 8 * i]);
    }
}

// Gather x = [latents|actions] rows into padded fp16 d_xbuf
__global__ __launch_bounds__(256) void k_gx(const float* __restrict__ latents,
                                            const float* __restrict__ actions) {
    __shared__ int rid_s[128];
    __shared__ Meta sm;
    int tid = threadIdx.x, t = blockIdx.x;
    if (tid == 0) sm = tile_meta(t);
    __syncthreads();
    if (sm.p < 0) return;
    if (tid < 128) rid_s[tid] = (tid < sm.vrows) ? d_row_id[sm.ridbase + tid] : -1;
    __syncthreads();
    __half* xb = d_xbuf + (size_t)t * 128 * XDIM;
#pragma unroll
    for (int tt = 0; tt < 36; tt++) {
        int j = tid + tt * 256;              // 128 rows * 72 segs of 8 floats
        int row = j / 72, s = j % 72;
        int b = rid_s[row];
        float4 v0 = make_float4(0.f, 0.f, 0.f, 0.f), v1 = v0;
        if (b >= 0) {
            if (s < 64) {
                const float* src = latents + (size_t)b * DDIM + s * 8;
                v0 = *(const float4*)(src); v1 = *(const float4*)(src + 4);
            } else {
                const float* src = actions + (size_t)b * ADIM + (s - 64) * 8;
                v0 = *(const float4*)(src); v1 = *(const float4*)(src + 4);
            }
        }
        __half2 h0 = __floats2half2_rn(v0.x, v0.y);
        __half2 h1 = __floats2half2_rn(v0.z, v0.w);
        __half2 h2 = __floats2half2_rn(v1.x, v1.y);
        __half2 h3 = __floats2half2_rn(v1.z, v1.w);
        __half2* dst = (__half2*)(xb + (size_t)row * XDIM + s * 8);
        dst[0] = h0; dst[1] = h1; dst[2] = h2; dst[3] = h3;
    }
}

// ---------------- SMEM layout ----------------
// tiles: 128 rows x 32 k fp16; row stride 80 bytes (64 data + 16 pad)
#define ROWB    80
#define TBYTES  (128 * ROWB)          // 10240
#define STAGE   (2 * TBYTES)          // 20480
#define NSTG    4
#define SMEM_TOTAL (NSTG * STAGE)     // 81920

// ---------------- fp16 GEMM: 128x128 CTA tile, 8 warps of 64x32, BK=32, 4-stage ----------------
template <int LAYER>
__global__ __launch_bounds__(256, 2) void k_mma(
    const float* __restrict__ bias, float* __restrict__ out)
{
    constexpr int KDIM = (LAYER == 1) ? XDIM : HDIM;
    constexpr int NDIM = (LAYER == 1) ? HDIM : DDIM;
    constexpr int KT   = KDIM / 32;

    extern __shared__ char smem[];
    __shared__ int rid_s[128];
    __shared__ Meta sm;
    const uint32_t sb = smem_u32(smem);
    const int tid = threadIdx.x;
    const int t = blockIdx.y;

    if (tid == 0) sm = tile_meta(t);
    __syncthreads();
    const int p = sm.p;
    if (p < 0) return;
    if (LAYER == 2 && tid < 128)
        rid_s[tid] = (tid < sm.vrows) ? d_row_id[sm.ridbase + tid] : -1;
    const int n0 = blockIdx.x * 128;
    const int row0 = t * 128;

    // ---- hoisted streaming pointers: 128 rows x 4 segs of 16B (8 halves) ----
    const int lrow = tid >> 2, lseg = tid & 3;       // 64 rows per pass, 2 passes
    const __half* aptr = ((LAYER == 1) ? d_xbuf : d_hbuf)
                         + (size_t)(row0 + lrow) * KDIM + lseg * 8;
    const __half* bptr = ((LAYER == 1)
                         ? d_w1t + (size_t)p * HDIM * XDIM
                         : d_w2t + (size_t)p * DDIM * HDIM)
                         + (size_t)(n0 + lrow) * KDIM + lseg * 8;
    const uint32_t ldst = (uint32_t)lrow * ROWB + lseg * 16;

    auto load = [&](int slot) {
        const uint32_t ab = sb + slot * STAGE;
#pragma unroll
        for (int tt = 0; tt < 2; tt++)
            cpasync16(ab + ldst + tt * (64 * ROWB), aptr + (size_t)tt * 64 * KDIM);
#pragma unroll
        for (int tt = 0; tt < 2; tt++)
            cpasync16(ab + TBYTES + ldst + tt * (64 * ROWB), bptr + (size_t)tt * 64 * KDIM);
        CP_COMMIT();
        aptr += 32; bptr += 32;
    };

    // ---- fragment geometry: 2(m) x 4(n) warps, 64x32 tiles ----
    const int lane = tid & 31, warp = tid >> 5;
    const int wm = warp >> 2, wn = warp & 3;
    const int g = lane >> 2, tq = lane & 3;
    const uint32_t fo = (uint32_t)(lane & 15) * ROWB + (uint32_t)(lane & 16);
    const uint32_t ao = (uint32_t)(wm * 64) * ROWB + fo;
    const uint32_t bo = (uint32_t)(wn * 32) * ROWB + fo;

    float acc[4][4][4];
#pragma unroll
    for (int i = 0; i < 4; i++)
#pragma unroll
        for (int j = 0; j < 4; j++)
#pragma unroll
            for (int q = 0; q < 4; q++) acc[i][j][q] = 0.f;

    load(0); load(1); load(2); load(3);

    for (int c = 0; c < KT; c++) {
        if (c + 4 <= KT)      CP_WAIT(3);
        else if (c + 3 == KT) CP_WAIT(2);
        else if (c + 2 == KT) CP_WAIT(1);
        else                  CP_WAIT(0);
        __syncthreads();

        const uint32_t Ab = sb + (c & 3) * STAGE;
        const uint32_t Bb = Ab + TBYTES;
#pragma unroll
        for (int ks = 0; ks < 2; ks++) {        // two k16 steps
            uint32_t a[4][4], b[2][4];
#pragma unroll
            for (int i = 0; i < 4; i++)
                ldsm4(a[i], Ab + ao + (uint32_t)(i * 16 * ROWB + ks * 32));
#pragma unroll
            for (int jj = 0; jj < 2; jj++)
                ldsm4(b[jj], Bb + bo + (uint32_t)(jj * 16 * ROWB + ks * 32));
#pragma unroll
            for (int i = 0; i < 4; i++)
#pragma unroll
                for (int jj = 0; jj < 2; jj++) {
                    mma_f16(acc[i][2 * jj],     a[i], b[jj][0], b[jj][2]);
                    mma_f16(acc[i][2 * jj + 1], a[i], b[jj][1], b[jj][3]);
                }
        }
        __syncthreads();
        if (c + 4 < KT) load(c & 3);
    }

    // ---- epilogue ----
    const float* bp = bias + p * NDIM + n0;
    if (LAYER == 1) {
        __half* hb = d_hbuf + (size_t)row0 * HDIM + n0;
#pragma unroll
        for (int j = 0; j < 4; j++) {
            int col = wn * 32 + j * 8 + 2 * tq;
            float bx = bp[col], by = bp[col + 1];
#pragma unroll
            for (int i = 0; i < 4; i++) {
                int r0 = wm * 64 + i * 16 + g;
                __half2 v0 = __floats2half2_rn(fmaxf(acc[i][j][0] + bx, 0.f),
                                               fmaxf(acc[i][j][1] + by, 0.f));
                __half2 v1 = __floats2half2_rn(fmaxf(acc[i][j][2] + bx, 0.f),
                                               fmaxf(acc[i][j][3] + by, 0.f));
                *(__half2*)(hb + (size_t)r0 * HDIM + col)       = v0;
                *(__half2*)(hb + (size_t)(r0 + 8) * HDIM + col) = v1;
            }
        }
    } else {
#pragma unroll
        for (int i = 0; i < 4; i++) {
            int r0 = wm * 64 + i * 16 + g;
            int b0 = rid_s[r0], b1i = rid_s[r0 + 8];
#pragma unroll
            for (int j = 0; j < 4; j++) {
                int col = wn * 32 + j * 8 + 2 * tq;
                float bx = bp[col], by = bp[col + 1];
                if (b0 >= 0)
                    *(float2*)(out + (size_t)b0 * DDIM + n0 + col) =
                        make_float2(acc[i][j][0] + bx, acc[i][j][1] + by);
                if (b1i >= 0)
                    *(float2*)(out + (size_t)b1i * DDIM + n0 + col) =
                        make_float2(acc[i][j][2] + bx, acc[i][j][3] + by);
            }
        }
    }
}

// ---------------- launch ----------------
extern "C" void kernel_launch(void* const* d_in, const int* in_sizes, int n_in,
                              void* d_out, int out_size)
{
    const float* latents = (const float*)d_in[0];
    const float* actions = (const float*)d_in[1];
    const void*  pidx    = d_in[2];
    const float* W1      = (const float*)d_in[3];
    const float* b1      = (const float*)d_in[4];
    const float* W2      = (const float*)d_in[5];
    const float* b2      = (const float*)d_in[6];
    float*       out     = (float*)d_out;

    int B = in_sizes[0] / DDIM;               // 16384
    int gy = B / 128 + PNUM - 1;              // 135 max tiles

    cudaFuncSetAttribute(k_mma<1>, cudaFuncAttributeMaxDynamicSharedMemorySize, SMEM_TOTAL);
    cudaFuncSetAttribute(k_mma<2>, cudaFuncAttributeMaxDynamicSharedMemorySize, SMEM_TOTAL);

    k_init<<<1, 32>>>((const int*)pidx, B);
    k_scan<<<(B + 255) / 256, 256>>>(pidx, B);
    k_tw<<<W1BLK + W2BLK, 256>>>(W1, W2);
    k_gx<<<gy, 256>>>(latents, actions);

    k_mma<1><<<dim3(HDIM / 128, gy), 256, SMEM_TOTAL>>>(b1, nullptr);
    k_mma<2><<<dim3(DDIM / 128, gy), 256, SMEM_TOTAL>>>(b2, out);
}

// round 8
// speedup vs baseline: 1.7904x; 1.2379x over previous
#include <cuda_runtime.h>
#include <cuda_fp16.h>
#include <cstdint>

#define PNUM 8
#define DDIM 512
#define ADIM 64
#define XDIM 576
#define HDIM 1024
#define BCAP 16384
#define MAXT 136

// ---------------- device scratch ----------------
__device__ int d_cursor[PNUM];
__device__ int d_is64;
__device__ int d_row_id[PNUM * BCAP];
__device__ __align__(128) __half d_xbuf[(size_t)MAXT * 128 * XDIM];   // fp16 gathered x
__device__ __align__(128) __half d_hbuf[(size_t)MAXT * 128 * HDIM];   // fp16 h
__device__ __align__(128) __half d_w1h[(size_t)PNUM * XDIM * HDIM];   // [p][k][n] fp16 (natural)
__device__ __align__(128) __half d_w2h[(size_t)PNUM * HDIM * DDIM];   // [p][k][n] fp16 (natural)

// ---------------- helpers ----------------
__device__ __forceinline__ void cpasync16(uint32_t dst, const void* src) {
    asm volatile("cp.async.cg.shared.global [%0], [%1], 16;\n"
                 :: "r"(dst), "l"(src) : "memory");
}
#define CP_COMMIT() asm volatile("cp.async.commit_group;\n" ::: "memory")
#define CP_WAIT(n)  asm volatile("cp.async.wait_group " #n ";\n" ::: "memory")

__device__ __forceinline__ uint32_t smem_u32(const void* p) {
    uint32_t a;
    asm("{ .reg .u64 t; cvta.to.shared.u64 t, %1; cvt.u32.u64 %0, t; }" : "=r"(a) : "l"(p));
    return a;
}
__device__ __forceinline__ void ldsm4(uint32_t* r, uint32_t addr) {
    asm volatile("ldmatrix.sync.aligned.m8n8.x4.shared.b16 {%0,%1,%2,%3}, [%4];"
                 : "=r"(r[0]), "=r"(r[1]), "=r"(r[2]), "=r"(r[3]) : "r"(addr));
}
__device__ __forceinline__ void ldsm4t(uint32_t* r, uint32_t addr) {
    asm volatile("ldmatrix.sync.aligned.m8n8.x4.trans.shared.b16 {%0,%1,%2,%3}, [%4];"
                 : "=r"(r[0]), "=r"(r[1]), "=r"(r[2]), "=r"(r[3]) : "r"(addr));
}
__device__ __forceinline__ void mma_f16(float* c, const uint32_t* a, uint32_t b0, uint32_t b1) {
    asm volatile(
        "mma.sync.aligned.m16n8k16.row.col.f32.f16.f16.f32 "
        "{%0,%1,%2,%3}, {%4,%5,%6,%7}, {%8,%9}, {%0,%1,%2,%3};"
        : "+f"(c[0]), "+f"(c[1]), "+f"(c[2]), "+f"(c[3])
        : "r"(a[0]), "r"(a[1]), "r"(a[2]), "r"(a[3]), "r"(b0), "r"(b1));
}
__device__ __forceinline__ int get_pidx(const void* pi, int b) {
    if (d_is64) return (int)(((const long long*)pi)[b]);
    return ((const int*)pi)[b];
}

struct Meta { int p, vrows, ridbase; };
__device__ __forceinline__ Meta tile_meta(int t) {
    int acc = 0, p = -1, lt = 0, c = 0;
#pragma unroll
    for (int q = 0; q < PNUM; q++) {
        int cq = d_cursor[q];
        int nt = (cq + 127) >> 7;
        if (p < 0 && t < acc + nt) { p = q; lt = t - acc; c = cq; }
        acc += nt;
    }
    Meta m; m.p = p;
    if (p >= 0) {
        int rem = c - lt * 128;
        m.vrows = rem < 128 ? rem : 128;
        m.ridbase = p * BCAP + lt * 128;
    } else { m.vrows = 0; m.ridbase = 0; }
    return m;
}

// ---------------- setup ----------------
__global__ void k_init(const int* pi32, int B) {
    int t = threadIdx.x;
    if (t < PNUM) d_cursor[t] = 0;
    int n = B < 64 ? B : 64;
    int bad = 0;
#pragma unroll
    for (int r = 0; r < 2; r++) {
        int i = t + 32 * r;
        if (i < n) {
            int lo = pi32[2 * i], hi = pi32[2 * i + 1];
            bad |= (hi != 0) || (lo < 0) || (lo >= PNUM);
        }
    }
    unsigned m = __ballot_sync(0xFFFFFFFF, bad);
    if (t == 0) d_is64 = (m == 0) ? 1 : 0;
}
__global__ void k_scan(const void* __restrict__ pi, int B) {
    int b = blockIdx.x * blockDim.x + threadIdx.x;
    if (b < B) {
        int p = get_pidx(pi, b);
        int pos = atomicAdd(&d_cursor[p], 1);
        d_row_id[p * BCAP + pos] = b;
    }
}

// ---------------- streaming fp32 -> fp16 weight convert (layout preserved) ----------------
#define W1F4 ((PNUM * XDIM * HDIM) / 4)   // 1179648
#define W2F4 ((PNUM * HDIM * DDIM) / 4)   // 1048576
#define WF4  (W1F4 + W2F4)                // 2228224
__global__ __launch_bounds__(256) void k_w16(const float4* __restrict__ W1,
                                             const float4* __restrict__ W2) {
    size_t i0 = ((size_t)blockIdx.x * 256 + threadIdx.x) * 4;
#pragma unroll
    for (int u = 0; u < 4; u++) {
        size_t i = i0 + u;
        if (i >= WF4) return;
        float4 v;
        __half* dst;
        if (i < W1F4) { v = W1[i]; dst = d_w1h + i * 4; }
        else          { size_t j = i - W1F4; v = W2[j]; dst = d_w2h + j * 4; }
        __half2 h0 = __floats2half2_rn(v.x, v.y);
        __half2 h1 = __floats2half2_rn(v.z, v.w);
        uint2 o = make_uint2(*(uint32_t*)&h0, *(uint32_t*)&h1);
        *(uint2*)dst = o;
    }
}

// ---------------- gather x rows into fp16 d_xbuf (4 blocks per tile) ----------------
__global__ __launch_bounds__(256) void k_gx(const float* __restrict__ latents,
                                            const float* __restrict__ actions) {
    __shared__ int rid_s[32];
    __shared__ Meta sm;
    int tid = threadIdx.x;
    int t = blockIdx.x >> 2, q = blockIdx.x & 3;
    if (tid == 0) sm = tile_meta(t);
    __syncthreads();
    if (sm.p < 0) return;
    int rbase = q * 32;
    if (tid < 32)
        rid_s[tid] = (rbase + tid < sm.vrows) ? d_row_id[sm.ridbase + rbase + tid] : -1;
    __syncthreads();
    __half* xb = d_xbuf + ((size_t)t * 128 + rbase) * XDIM;
#pragma unroll
    for (int tt = 0; tt < 9; tt++) {
        int j = tid + tt * 256;              // 32 rows * 72 segs of 8 floats
        int row = j / 72, s = j % 72;
        int b = rid_s[row];
        float4 v0 = make_float4(0.f, 0.f, 0.f, 0.f), v1 = v0;
        if (b >= 0) {
            const float* src = (s < 64) ? latents + (size_t)b * DDIM + s * 8
                                        : actions + (size_t)b * ADIM + (s - 64) * 8;
            v0 = *(const float4*)(src); v1 = *(const float4*)(src + 4);
        }
        __half2 h0 = __floats2half2_rn(v0.x, v0.y);
        __half2 h1 = __floats2half2_rn(v0.z, v0.w);
        __half2 h2 = __floats2half2_rn(v1.x, v1.y);
        __half2 h3 = __floats2half2_rn(v1.z, v1.w);
        __half2* dst = (__half2*)(xb + (size_t)row * XDIM + s * 8);
        dst[0] = h0; dst[1] = h1; dst[2] = h2; dst[3] = h3;
    }
}

// ---------------- SMEM layout ----------------
// A: 128 m-rows x 32 k halves, stride 80B  (64 data + 16 pad)
// B: 32 k-rows x 128 n halves, stride 272B (256 data + 16 pad -> conflict-free ldsm.trans)
#define AROWB   80
#define ABYTES  (128 * AROWB)         // 10240
#define BROWB   272
#define BBYTES  (32 * BROWB)          // 8704
#define STAGE   (ABYTES + BBYTES)     // 18944
#define NSTG    4
#define SMEM_TOTAL (NSTG * STAGE)     // 75776

// ---------------- fp16 GEMM: 128x128 CTA, 8 warps of 64x32, BK=32, 4-stage ----------------
template <int LAYER>
__global__ __launch_bounds__(256, 2) void k_mma(
    const float* __restrict__ bias, float* __restrict__ out)
{
    constexpr int KDIM = (LAYER == 1) ? XDIM : HDIM;
    constexpr int NDIM = (LAYER == 1) ? HDIM : DDIM;
    constexpr int KT   = KDIM / 32;

    extern __shared__ char smem[];
    __shared__ int rid_s[128];
    __shared__ Meta sm;
    const uint32_t sb = smem_u32(smem);
    const int tid = threadIdx.x;
    const int t = blockIdx.y;

    if (tid == 0) sm = tile_meta(t);
    __syncthreads();
    const int p = sm.p;
    if (p < 0) return;
    if (LAYER == 2 && tid < 128)
        rid_s[tid] = (tid < sm.vrows) ? d_row_id[sm.ridbase + tid] : -1;
    const int n0 = blockIdx.x * 128;
    const int row0 = t * 128;

    // ---- streaming pointers ----
    // A: 128 rows x 4 segs of 16B (2 passes of 64 rows)
    const int arow = tid >> 2, aseg = tid & 3;
    const __half* aptr = ((LAYER == 1) ? d_xbuf : d_hbuf)
                         + (size_t)(row0 + arow) * KDIM + aseg * 8;
    const uint32_t adst = (uint32_t)arow * AROWB + aseg * 16;
    // B: 32 k-rows x 16 segs of 16B (2 passes of 16 rows), natural [k][n] weights
    const int brow = tid >> 4, bseg = tid & 15;
    const __half* bptr = ((LAYER == 1) ? d_w1h + (size_t)p * XDIM * HDIM
                                       : d_w2h + (size_t)p * HDIM * DDIM)
                         + (size_t)brow * NDIM + n0 + bseg * 8;
    const uint32_t bdst = (uint32_t)brow * BROWB + bseg * 16;

    auto load = [&](int slot) {
        const uint32_t ab = sb + slot * STAGE;
#pragma unroll
        for (int tt = 0; tt < 2; tt++)
            cpasync16(ab + adst + tt * (64 * AROWB), aptr + (size_t)tt * 64 * KDIM);
#pragma unroll
        for (int tt = 0; tt < 2; tt++)
            cpasync16(ab + ABYTES + bdst + tt * (16 * BROWB), bptr + (size_t)tt * 16 * NDIM);
        CP_COMMIT();
        aptr += 32;
        bptr += (size_t)32 * NDIM;
    };

    // ---- fragment geometry: 2(m) x 4(n) warps, 64x32 warp tiles ----
    const int lane = tid & 31, warp = tid >> 5;
    const int wm = warp >> 2, wn = warp & 3;
    const int g = lane >> 2, tq = lane & 3;
    // A (non-trans, [m][k]): lanes 0-15 rows m0-15 @k0-7, lanes 16-31 @k8-15
    const uint32_t ao = (uint32_t)(wm * 64) * AROWB
                      + (uint32_t)(lane & 15) * AROWB + (uint32_t)(lane & 16);
    // B (trans, [k][n]): lanes (l&7)+((l>>3)&1)*8 k-rows, (l>>4) selects n8-block
    const uint32_t bo = (uint32_t)((lane & 7) + ((lane >> 3) & 1) * 8) * BROWB
                      + (uint32_t)((lane >> 4) & 1) * 16
                      + (uint32_t)(wn * 32) * 2;

    float acc[4][4][4];
#pragma unroll
    for (int i = 0; i < 4; i++)
#pragma unroll
        for (int j = 0; j < 4; j++)
#pragma unroll
            for (int q = 0; q < 4; q++) acc[i][j][q] = 0.f;

    load(0); load(1); load(2); load(3);

    for (int c = 0; c < KT; c++) {
        if (c + 4 <= KT)      CP_WAIT(3);
        else if (c + 3 == KT) CP_WAIT(2);
        else if (c + 2 == KT) CP_WAIT(1);
        else                  CP_WAIT(0);
        __syncthreads();

        const uint32_t Ab = sb + (c & 3) * STAGE;
        const uint32_t Bb = Ab + ABYTES;
#pragma unroll
        for (int ks = 0; ks < 2; ks++) {        // two k16 steps per 32-chunk
            uint32_t a[4][4], b[2][4];
#pragma unroll
            for (int i = 0; i < 4; i++)
                ldsm4(a[i], Ab + ao + (uint32_t)(i * 16 * AROWB + ks * 32));
#pragma unroll
            for (int jj = 0; jj < 2; jj++)      // each covers n16 (two n8 blocks)
                ldsm4t(b[jj], Bb + bo + (uint32_t)(ks * 16 * BROWB + jj * 32));
#pragma unroll
            for (int i = 0; i < 4; i++)
#pragma unroll
                for (int jj = 0; jj < 2; jj++) {
                    mma_f16(acc[i][2 * jj],     a[i], b[jj][0], b[jj][1]);
                    mma_f16(acc[i][2 * jj + 1], a[i], b[jj][2], b[jj][3]);
                }
        }
        __syncthreads();
        if (c + 4 < KT) load(c & 3);
    }

    // ---- epilogue ----
    const float* bp = bias + p * NDIM + n0;
    if (LAYER == 1) {
        __half* hb = d_hbuf + (size_t)row0 * HDIM + n0;
#pragma unroll
        for (int j = 0; j < 4; j++) {
            int col = wn * 32 + j * 8 + 2 * tq;
            float bx = bp[col], by = bp[col + 1];
#pragma unroll
            for (int i = 0; i < 4; i++) {
                int r0 = wm * 64 + i * 16 + g;
                __half2 v0 = __floats2half2_rn(fmaxf(acc[i][j][0] + bx, 0.f),
                                               fmaxf(acc[i][j][1] + by, 0.f));
                __half2 v1 = __floats2half2_rn(fmaxf(acc[i][j][2] + bx, 0.f),
                                               fmaxf(acc[i][j][3] + by, 0.f));
                *(__half2*)(hb + (size_t)r0 * HDIM + col)       = v0;
                *(__half2*)(hb + (size_t)(r0 + 8) * HDIM + col) = v1;
            }
        }
    } else {
#pragma unroll
        for (int i = 0; i < 4; i++) {
            int r0 = wm * 64 + i * 16 + g;
            int b0 = rid_s[r0], b1i = rid_s[r0 + 8];
#pragma unroll
            for (int j = 0; j < 4; j++) {
                int col = wn * 32 + j * 8 + 2 * tq;
                float bx = bp[col], by = bp[col + 1];
                if (b0 >= 0)
                    *(float2*)(out + (size_t)b0 * DDIM + n0 + col) =
                        make_float2(acc[i][j][0] + bx, acc[i][j][1] + by);
                if (b1i >= 0)
                    *(float2*)(out + (size_t)b1i * DDIM + n0 + col) =
                        make_float2(acc[i][j][2] + bx, acc[i][j][3] + by);
            }
        }
    }
}

// ---------------- launch ----------------
extern "C" void kernel_launch(void* const* d_in, const int* in_sizes, int n_in,
                              void* d_out, int out_size)
{
    const float* latents = (const float*)d_in[0];
    const float* actions = (const float*)d_in[1];
    const void*  pidx    = d_in[2];
    const float* W1      = (const float*)d_in[3];
    const float* b1      = (const float*)d_in[4];
    const float* W2      = (const float*)d_in[5];
    const float* b2      = (const float*)d_in[6];
    float*       out     = (float*)d_out;

    int B = in_sizes[0] / DDIM;               // 16384
    int gy = B / 128 + PNUM - 1;              // 135 max tiles

    cudaFuncSetAttribute(k_mma<1>, cudaFuncAttributeMaxDynamicSharedMemorySize, SMEM_TOTAL);
    cudaFuncSetAttribute(k_mma<2>, cudaFuncAttributeMaxDynamicSharedMemorySize, SMEM_TOTAL);

    k_init<<<1, 32>>>((const int*)pidx, B);
    k_scan<<<(B + 255) / 256, 256>>>(pidx, B);
    k_w16<<<(WF4 + 1023) / 1024, 256>>>((const float4*)W1, (const float4*)W2);
    k_gx<<<4 * gy, 256>>>(latents, actions);

    k_mma<1><<<dim3(HDIM / 128, gy), 256, SMEM_TOTAL>>>(b1, nullptr);
    k_mma<2><<<dim3(DDIM / 128, gy), 256, SMEM_TOTAL>>>(b2, out);
}